// round 14
// baseline (speedup 1.0000x reference)
#include <cuda_runtime.h>
#include <cmath>

#define B 64
#define C 32
#define HW 16
#define IMG (C*HW*HW)        // 8192
#define TOT (B*IMG)          // 524288
#define NE 4096
#define NIDX 21824
#define ROWLEN 341
#define TCODES 128

// ---------------- scratch (no allocations allowed) ----------------
__device__ float g_zres[TOT];
__device__ float g_r[TOT];            // only scales 0..1 use this
__device__ float g_qup[TOT];          // layout [b][y][x][c] (channel-last)
__device__ float g_hesq[NE];          // 0.5*||e||^2
__device__ unsigned long long g_res64[NIDX];
__device__ float g_losspart[5*512];
__device__ int   g_itab[4][16][4];
__device__ float g_wtab[4][16][4];

// ---------------- helpers ----------------
__device__ __forceinline__ float cubicw(float x){
    const float A = -0.75f;
    x = fabsf(x);
    if (x <= 1.f) return ((A + 2.f)*x - (A + 3.f))*x*x + 1.f;
    if (x < 2.f)  return A*(((x - 5.f)*x + 8.f)*x - 4.f);
    return 0.f;
}
__device__ __forceinline__ void ffma2(unsigned long long &d, unsigned long long a, unsigned long long b){
    asm("fma.rn.f32x2 %0, %1, %2, %0;" : "+l"(d) : "l"(a), "l"(b));
}
__device__ __forceinline__ unsigned long long pk2(float a, float b){
    return ((unsigned long long)__float_as_uint(b) << 32) | (unsigned long long)__float_as_uint(a);
}
__device__ __forceinline__ float lo2(unsigned long long v){ return __uint_as_float((unsigned)v); }
__device__ __forceinline__ float hi2(unsigned long long v){ return __uint_as_float((unsigned)(v >> 32)); }
__device__ __forceinline__ unsigned ford(float f){
    unsigned u = __float_as_uint(f);
    return (u & 0x80000000u) ? ~u : (u | 0x80000000u);
}

// pooled residual row loader. fmode: 0 = g_r, 1 = f=1, 2 = f=2, 3 = f=4
__device__ __forceinline__ void load_r(int row, int fmode, float* r){
    if (fmode == 1){
        int bb = row >> 8, rem = row & 255;
        const float* p = g_zres + bb*IMG + rem;
        #pragma unroll
        for (int c = 0; c < C; c++) r[c] = p[c*256];
    } else if (fmode == 2){
        int bb = row >> 6, rem = row & 63;
        int y = rem >> 3, x = rem & 7;
        const float* p = g_zres + bb*IMG + (2*y)*16 + 2*x;
        #pragma unroll
        for (int c = 0; c < C; c++){
            const float* q = p + c*256;
            r[c] = (q[0] + q[1] + q[16] + q[17]) * 0.25f;
        }
    } else if (fmode == 3){
        int bb = row >> 4, rem = row & 15;
        int y = rem >> 2, x = rem & 3;
        const float* p = g_zres + bb*IMG + (4*y)*16 + 4*x;
        #pragma unroll
        for (int c = 0; c < C; c++){
            const float* q = p + c*256;
            float s = 0.f;
            #pragma unroll
            for (int dy = 0; dy < 4; dy++){
                s += q[dy*16 + 0]; s += q[dy*16 + 1]; s += q[dy*16 + 2]; s += q[dy*16 + 3];
            }
            r[c] = s * 0.0625f;
        }
    } else {
        const float4* rp = (const float4*)(g_r + row*C);
        #pragma unroll
        for (int k = 0; k < 8; k++){
            float4 v = rp[k];
            r[4*k+0] = v.x; r[4*k+1] = v.y; r[4*k+2] = v.z; r[4*k+3] = v.w;
        }
    }
}

// ---------------- setup (also pools scale 0, whose input is raw z) ----------------
__global__ void setup_kernel(const float* __restrict__ z, const float* __restrict__ emb){
    int t = blockIdx.x*blockDim.x + threadIdx.x;
    if (t < TOT) g_zres[t] = z[t];
    if (t < NIDX) g_res64[t] = 0xFFFFFFFFFFFFFFFFull;
    if (t < NE){
        float s = 0.f;
        #pragma unroll
        for (int k = 0; k < C; k++){ float e = emb[t*C + k]; s += e*e; }
        g_hesq[t] = 0.5f*s;
    }
    if (t < 2048){   // pool scale 0 (f=16): r[b][c] = mean z[b][c][:][:]
        int b = t >> 5, c = t & 31;
        const float4* p = (const float4*)(z + (b*C + c)*256);
        float s = 0.f;
        for (int k = 0; k < 64; k++){
            float4 v = p[k];
            s += v.x + v.y + v.z + v.w;
        }
        g_r[(b)*C + c] = s * (1.f/256.f);
    }
    if (t < 256){
        int s = t >> 6, rem = t & 63, Y = rem >> 2, a = rem & 3;
        int ph = 1 << s;
        float scale = (float)ph / 16.f;
        float src = ((float)Y + 0.5f)*scale - 0.5f;
        float i0 = floorf(src);
        float fr = src - i0;
        int off = a - 1;
        int idx = (int)i0 + off;
        idx = min(max(idx, 0), ph - 1);
        g_itab[s][Y][a] = idx;
        g_wtab[s][Y][a] = cubicw(fr - (float)off);
    }
}

// ---------------- area pool to [N][C] channel-last (scale 1 only) ----------------
__global__ void pool_kernel(int ph){
    int t = blockIdx.x*blockDim.x + threadIdx.x;
    int N = B*ph*ph;
    if (t >= N*C) return;
    int n = t >> 5, c = t & 31;
    int pp = ph*ph;
    int b = n / pp, rem = n % pp, y = rem / ph, x = rem % ph;
    int f = HW / ph;
    const float* base = g_zres + ((b*C + c)*HW + y*f)*HW + x*f;
    float s = 0.f;
    for (int dy = 0; dy < f; dy++)
        for (int dx = 0; dx < f; dx++)
            s += base[dy*HW + dx];
    g_r[n*C + c] = s * (1.f / (float)(f*f));
}

// ---------------- code search: score = 0.5||e||^2 - r.e, FFMA2, TROWS rows/thread ----------------
template<int TROWS>
__global__ __launch_bounds__(128) void argmin_kernel(const float* __restrict__ emb, int N, int chunk,
                                                     int base, int fmode){
    __shared__ __align__(16) float et[C*TCODES];   // transposed [dim][code]
    __shared__ __align__(16) float hs[TCODES];
    int tid = threadIdx.x;
    int row0 = blockIdx.x*(128*TROWS) + tid;
    int cbase = blockIdx.y * chunk;

    unsigned long long nrp[TROWS][C];    // packed {-r_d, -r_d}
    bool act[TROWS];
    #pragma unroll
    for (int tr = 0; tr < TROWS; tr++){
        int row = row0 + tr*128;
        act[tr] = row < N;
        if (act[tr]){
            float r[C];
            load_r(row, fmode, r);
            #pragma unroll
            for (int c = 0; c < C; c++) nrp[tr][c] = pk2(-r[c], -r[c]);
        }
    }
    float best[TROWS]; int bcode[TROWS];
    #pragma unroll
    for (int tr = 0; tr < TROWS; tr++){ best[tr] = 3.4e38f; bcode[tr] = 0; }

    for (int tb = 0; tb < chunk; tb += TCODES){
        int code = cbase + tb + tid;
        const float4* src = (const float4*)(emb + code*C);
        __syncthreads();   // prior tile fully consumed
        #pragma unroll
        for (int k = 0; k < 8; k++){
            float4 v = src[k];
            et[(4*k+0)*TCODES + tid] = v.x;
            et[(4*k+1)*TCODES + tid] = v.y;
            et[(4*k+2)*TCODES + tid] = v.z;
            et[(4*k+3)*TCODES + tid] = v.w;
        }
        hs[tid] = g_hesq[code];
        __syncthreads();

        for (int jj = 0; jj < TCODES; jj += 8){
            const ulonglong2* h2 = (const ulonglong2*)(hs + jj);
            ulonglong2 ha = h2[0], hb = h2[1];
            unsigned long long acc[TROWS][4];
            #pragma unroll
            for (int tr = 0; tr < TROWS; tr++){
                acc[tr][0] = ha.x; acc[tr][1] = ha.y; acc[tr][2] = hb.x; acc[tr][3] = hb.y;
            }
            #pragma unroll
            for (int d = 0; d < C; d++){
                const ulonglong2* e2 = (const ulonglong2*)(et + d*TCODES + jj);
                ulonglong2 ea = e2[0], eb = e2[1];
                #pragma unroll
                for (int tr = 0; tr < TROWS; tr++){
                    ffma2(acc[tr][0], nrp[tr][d], ea.x);
                    ffma2(acc[tr][1], nrp[tr][d], ea.y);
                    ffma2(acc[tr][2], nrp[tr][d], eb.x);
                    ffma2(acc[tr][3], nrp[tr][d], eb.y);
                }
            }
            #pragma unroll
            for (int tr = 0; tr < TROWS; tr++){
                float s[8] = {lo2(acc[tr][0]),hi2(acc[tr][0]),lo2(acc[tr][1]),hi2(acc[tr][1]),
                              lo2(acc[tr][2]),hi2(acc[tr][2]),lo2(acc[tr][3]),hi2(acc[tr][3])};
                #pragma unroll
                for (int k = 0; k < 8; k++){
                    int cc = cbase + tb + jj + k;
                    if (s[k] < best[tr]){ best[tr] = s[k]; bcode[tr] = cc; }
                }
            }
        }
    }
    #pragma unroll
    for (int tr = 0; tr < TROWS; tr++){
        if (act[tr]){
            unsigned long long key = ((unsigned long long)ford(best[tr]) << 32) | (unsigned)bcode[tr];
            atomicMin(&g_res64[base + row0 + tr*128], key);
        }
    }
}

// ---------------- separable staged gather (si<4) -> g_qup [b][y][x][c] ----------------
__global__ __launch_bounds__(256) void gather_sep_kernel(const float* __restrict__ emb,
        int si, int ph, int lph, int base){
    __shared__ int   s_code[64];
    __shared__ float s_q[64*17];          // [code][cl + pad]
    __shared__ float s_tmp[8*16*17];      // [py][x][cl + pad]
    int b = blockIdx.x, cg = blockIdx.y, t = threadIdx.x;
    int pp = ph*ph;

    if (t < pp) s_code[t] = (int)(g_res64[base + b*pp + t] & 0xFFFFFFFFull);
    __syncthreads();

    // stage q vectors: lanes vary cl -> coalesced emb reads
    for (int i = t; i < pp*16; i += 256){
        int cl = i & 15, code = i >> 4;
        s_q[code*17 + cl] = emb[s_code[code]*C + cg*16 + cl];
    }
    __syncthreads();

    // pass1: x-interp -> s_tmp[py][x][cl]
    int n1 = ph*256;
    for (int i = t; i < n1; i += 256){
        int cl = i & 15, x = (i >> 4) & 15, py = i >> 8;
        float acc = 0.f;
        #pragma unroll
        for (int ax = 0; ax < 4; ax++){
            int ix = g_itab[si][x][ax];
            acc += g_wtab[si][x][ax] * s_q[(py*ph + ix)*17 + cl];
        }
        s_tmp[(py*16 + x)*17 + cl] = acc;
    }
    __syncthreads();

    // pass2: y-interp -> g_qup[b][y][x][cg*16+cl] (coalesced)
    for (int i = t; i < 4096; i += 256){
        int cl = i & 15, x = (i >> 4) & 15, y = i >> 8;
        float acc = 0.f;
        #pragma unroll
        for (int ay = 0; ay < 4; ay++){
            int iy = g_itab[si][y][ay];
            acc += g_wtab[si][y][ay] * s_tmp[(iy*16 + x)*17 + cl];
        }
        g_qup[b*IMG + (y*16 + x)*32 + cg*16 + cl] = acc;
    }
}

// ---------------- direct gather (si=4): lanes vary c -> fully coalesced ----------------
__global__ void gather_direct_kernel(const float* __restrict__ emb, int base){
    int t = blockIdx.x*blockDim.x + threadIdx.x;
    if (t >= TOT) return;
    int c = t & 31, pix = (t >> 5) & 255, b = t >> 13;
    int code = (int)(g_res64[base + b*256 + pix] & 0xFFFFFFFFull);
    g_qup[t] = emb[code*C + c];   // g_qup [b][y][x][c]
}

// ---------------- Phi conv3x3, y-split: grid (B, 4og, 2yh), block 256 = x16*ocp8*yq2 ----------------
// Each thread: 1 oc x 4 y. s_in = 10-row halo slab [ci][row*16+x], ci stride 161.
__global__ __launch_bounds__(256) void conv_update_kernel(const float* __restrict__ z,
        const float* __restrict__ w, const float* __restrict__ bias, int si, float* __restrict__ out){
    __shared__ float s_in[C*161];       // [ci][row10*16 + x], pad 1 per ci
    __shared__ float s_w[C*9*8];        // [ci][ky*3+kx][oc_l]
    __shared__ float red[256];
    int b = blockIdx.x, og = blockIdx.y, yh = blockIdx.z, t = threadIdx.x;

    // load q_up rows [yh*8-1, yh*8+8] -> s_in[c][lr*16+x]; invalid rows never read (guards below)
    int rowbase = yh*8 - 1;
    for (int j = t; j < 1280; j += 256){
        int cq = j & 7, pl = j >> 3;          // pl = lr*16 + x, 0..159
        int gr = rowbase + (pl >> 4);
        if (gr >= 0 && gr < HW){
            float4 v = *(const float4*)(g_qup + b*IMG + (gr*16 + (pl & 15))*32 + cq*4);
            int c0 = cq*4;
            s_in[(c0+0)*161 + pl] = v.x;
            s_in[(c0+1)*161 + pl] = v.y;
            s_in[(c0+2)*161 + pl] = v.z;
            s_in[(c0+3)*161 + pl] = v.w;
        }
    }
    // weights: global [oc_l][ci][k] -> smem [ci][k][oc_l]
    for (int i = t; i < 8*C*9; i += 256){
        int oc_l = i / (C*9);
        int rem  = i - oc_l*(C*9);
        s_w[rem*8 + oc_l] = w[og*8*C*9 + i];
    }
    __syncthreads();

    int x    = t & 15;        // lanes vary x (+ ocp bit0) -> conflict-free/broadcast v loads
    int ocp  = (t >> 4) & 7;
    int yq   = t >> 7;        // 0..1
    int y0 = yh*8 + yq*4;     // global start row of this thread's 4 rows

    float acc[4] = {0.f, 0.f, 0.f, 0.f};

    for (int ci = 0; ci < C; ci++){
        const float* base_ci = s_in + ci*161;
        const float* wci = s_w + ci*72 + ocp;
        #pragma unroll
        for (int kx = 0; kx < 3; kx++){
            int xx = x + kx - 1;
            if (xx < 0 || xx >= HW) continue;   // zero pad
            // v[j] = input global row (y0-1+j) = local row (yq*4 + j)
            float v[6];
            v[0] = (y0 >= 1)     ? base_ci[(yq*4+0)*16 + xx] : 0.f;
            v[1] = base_ci[(yq*4+1)*16 + xx];
            v[2] = base_ci[(yq*4+2)*16 + xx];
            v[3] = base_ci[(yq*4+3)*16 + xx];
            v[4] = base_ci[(yq*4+4)*16 + xx];
            v[5] = (y0 + 4 < HW) ? base_ci[(yq*4+5)*16 + xx] : 0.f;
            #pragma unroll
            for (int ky = 0; ky < 3; ky++){
                float wv = wci[(ky*3 + kx)*8];
                #pragma unroll
                for (int i = 0; i < 4; i++) acc[i] += wv * v[i + ky];
            }
        }
    }

    int oc = og*8 + ocp;
    float bval = bias[oc];
    float ls = 0.f;
    int gbase = ((b*C + oc)*HW)*HW + x;
    #pragma unroll
    for (int i = 0; i < 4; i++){
        int y = y0 + i;
        int lr = yq*4 + i + 1;    // local row of y
        float qv = 0.5f*s_in[oc*161 + lr*16 + x] + 0.5f*(acc[i] + bval);
        int g = gbase + y*HW;
        float zr = g_zres[g] - qv;
        if (si < 4){
            g_zres[g] = zr;
        } else {
            out[g] = z[g] - zr;   // z_hat (straight-through value)
        }
        ls += zr*zr;              // (z_hat - z)^2 == zres_new^2
    }
    red[t] = ls;
    __syncthreads();
    for (int s = 128; s > 0; s >>= 1){
        if (t < s) red[t] += red[t+s];
        __syncthreads();
    }
    if (t == 0) g_losspart[si*512 + ((b*4 + og)*2 + yh)] = red[0];
}

// ---------------- final pack: loss (parallel reduce) + idx floats ----------------
__global__ void pack_kernel(float* __restrict__ out){
    int t = blockIdx.x*blockDim.x + threadIdx.x;
    if (blockIdx.x == 0){
        __shared__ float red[256];
        float s = 0.f;
        for (int i = threadIdx.x; i < 5*512; i += 256) s += g_losspart[i];
        red[threadIdx.x] = s;
        __syncthreads();
        for (int k = 128; k > 0; k >>= 1){
            if (threadIdx.x < k) red[threadIdx.x] += red[threadIdx.x + k];
            __syncthreads();
        }
        if (threadIdx.x == 0) out[TOT] = red[0] * (1.25f / ((float)TOT * 5.f));
    }
    if (t < NIDX){
        int base, pp, ofs_row;
        if      (t <   64){ base=0;    pp=1;   ofs_row=0;  }
        else if (t <  320){ base=64;   pp=4;   ofs_row=1;  }
        else if (t < 1344){ base=320;  pp=16;  ofs_row=5;  }
        else if (t < 5440){ base=1344; pp=64;  ofs_row=21; }
        else              { base=5440; pp=256; ofs_row=85; }
        int r = t - base;
        int bb = r / pp, p = r % pp;
        int code = (int)(g_res64[t] & 0xFFFFFFFFull);
        out[TOT + 1 + bb*ROWLEN + ofs_row + p] = (float)code;
    }
}

extern "C" void kernel_launch(void* const* d_in, const int* in_sizes, int n_in,
                              void* d_out, int out_size){
    // Bind inputs by element count: z=524288, emb=131072, phi_w=36864, phi_b=128 (all distinct).
    const float* z = 0; const float* emb = 0; const float* phi_w = 0; const float* phi_b = 0;
    for (int i = 0; i < n_in; i++){
        switch (in_sizes[i]){
            case 524288: z     = (const float*)d_in[i]; break;
            case 131072: emb   = (const float*)d_in[i]; break;
            case 36864:  phi_w = (const float*)d_in[i]; break;
            case 128:    phi_b = (const float*)d_in[i]; break;
            default: break;
        }
    }
    float* out = (float*)d_out;
    (void)out_size;

    setup_kernel<<<(TOT + 255)/256, 256>>>(z, emb);

    // numpy-exact Phi tick selection (float64 linspace semantics, first-wins argmin)
    double start = 1.0/12.0;
    double stop  = 1.0 - 1.0/12.0;
    double step  = (stop - start) / 3.0;
    double ticks[4];
    for (int i = 0; i < 4; i++) ticks[i] = (double)i * step + start;
    ticks[3] = stop;
    int pis[5];
    for (int si = 0; si < 5; si++){
        double target = (double)si / 4.0;
        int bestp = 0; double bestd = fabs(ticks[0] - target);
        for (int p = 1; p < 4; p++){
            double d = fabs(ticks[p] - target);
            if (d < bestd){ bestd = d; bestp = p; }
        }
        pis[si] = bestp;
    }

    const int scales[5] = {1, 2, 4, 8, 16};
    const int iofs[5]   = {0, 64, 320, 1344, 5440};
    const int splits[5] = {32, 32, 16, 16, 8};
    const int fmodes[5] = {0, 0, 3, 2, 1};

    for (int si = 0; si < 5; si++){
        int ph = scales[si];
        int N  = B*ph*ph;
        if (si == 1) pool_kernel<<<(N*C + 255)/256, 256>>>(ph);
        int chunk = NE/splits[si];
        if (si >= 3){
            dim3 g((N + 255)/256, splits[si]);
            argmin_kernel<2><<<g, 128>>>(emb, N, chunk, iofs[si], fmodes[si]);
        } else {
            dim3 g((N + 127)/128, splits[si]);
            argmin_kernel<1><<<g, 128>>>(emb, N, chunk, iofs[si], fmodes[si]);
        }
        if (si < 4)
            gather_sep_kernel<<<dim3(B, 2), 256>>>(emb, si, ph, si, iofs[si]);
        else
            gather_direct_kernel<<<(TOT + 255)/256, 256>>>(emb, iofs[si]);
        conv_update_kernel<<<dim3(B, 4, 2), 256>>>(z, phi_w + pis[si]*C*C*9, phi_b + pis[si]*C,
                                                   si, (si == 4) ? out : (float*)0);
    }
    pack_kernel<<<(NIDX + 255)/256, 256>>>(out);
}

// round 15
// speedup vs baseline: 1.1329x; 1.1329x over previous
#include <cuda_runtime.h>
#include <cmath>

#define B 64
#define C 32
#define HW 16
#define IMG (C*HW*HW)        // 8192
#define TOT (B*IMG)          // 524288
#define NE 4096
#define NIDX 21824
#define ROWLEN 341
#define TCODES 128

// dynamic smem floats: s_in 8224 | s_w 2304 | red 256 | s_code 256(int) | s_q 2112 | s_tmp 4224
#define SMEM_CONV ((8224 + 2304 + 256 + 256 + 2112 + 4224) * 4)

// ---------------- scratch (no allocations allowed) ----------------
__device__ float g_zres[TOT];
__device__ float g_r[TOT];            // only scales 0..1 use this
__device__ float g_hesq[NE];          // 0.5*||e||^2
__device__ unsigned long long g_res64[NIDX];
__device__ float g_losspart[5*256];
__device__ int   g_itab[4][16][4];
__device__ float g_wtab[4][16][4];

// ---------------- helpers ----------------
__device__ __forceinline__ float cubicw(float x){
    const float A = -0.75f;
    x = fabsf(x);
    if (x <= 1.f) return ((A + 2.f)*x - (A + 3.f))*x*x + 1.f;
    if (x < 2.f)  return A*(((x - 5.f)*x + 8.f)*x - 4.f);
    return 0.f;
}
__device__ __forceinline__ void ffma2(unsigned long long &d, unsigned long long a, unsigned long long b){
    asm("fma.rn.f32x2 %0, %1, %2, %0;" : "+l"(d) : "l"(a), "l"(b));
}
__device__ __forceinline__ unsigned long long pk2(float a, float b){
    return ((unsigned long long)__float_as_uint(b) << 32) | (unsigned long long)__float_as_uint(a);
}
__device__ __forceinline__ float lo2(unsigned long long v){ return __uint_as_float((unsigned)v); }
__device__ __forceinline__ float hi2(unsigned long long v){ return __uint_as_float((unsigned)(v >> 32)); }
__device__ __forceinline__ unsigned ford(float f){
    unsigned u = __float_as_uint(f);
    return (u & 0x80000000u) ? ~u : (u | 0x80000000u);
}

// pooled residual row loader. fmode: 0 = g_r, 1 = f=1, 2 = f=2, 3 = f=4
__device__ __forceinline__ void load_r(int row, int fmode, float* r){
    if (fmode == 1){
        int bb = row >> 8, rem = row & 255;
        const float* p = g_zres + bb*IMG + rem;
        #pragma unroll
        for (int c = 0; c < C; c++) r[c] = p[c*256];
    } else if (fmode == 2){
        int bb = row >> 6, rem = row & 63;
        int y = rem >> 3, x = rem & 7;
        const float* p = g_zres + bb*IMG + (2*y)*16 + 2*x;
        #pragma unroll
        for (int c = 0; c < C; c++){
            const float* q = p + c*256;
            r[c] = (q[0] + q[1] + q[16] + q[17]) * 0.25f;
        }
    } else if (fmode == 3){
        int bb = row >> 4, rem = row & 15;
        int y = rem >> 2, x = rem & 3;
        const float* p = g_zres + bb*IMG + (4*y)*16 + 4*x;
        #pragma unroll
        for (int c = 0; c < C; c++){
            const float* q = p + c*256;
            float s = 0.f;
            #pragma unroll
            for (int dy = 0; dy < 4; dy++){
                s += q[dy*16 + 0]; s += q[dy*16 + 1]; s += q[dy*16 + 2]; s += q[dy*16 + 3];
            }
            r[c] = s * 0.0625f;
        }
    } else {
        const float4* rp = (const float4*)(g_r + row*C);
        #pragma unroll
        for (int k = 0; k < 8; k++){
            float4 v = rp[k];
            r[4*k+0] = v.x; r[4*k+1] = v.y; r[4*k+2] = v.z; r[4*k+3] = v.w;
        }
    }
}

// ---------------- setup (also pools scale 0, whose input is raw z) ----------------
__global__ void setup_kernel(const float* __restrict__ z, const float* __restrict__ emb){
    int t = blockIdx.x*blockDim.x + threadIdx.x;
    if (t < TOT) g_zres[t] = z[t];
    if (t < NIDX) g_res64[t] = 0xFFFFFFFFFFFFFFFFull;
    if (t < NE){
        float s = 0.f;
        #pragma unroll
        for (int k = 0; k < C; k++){ float e = emb[t*C + k]; s += e*e; }
        g_hesq[t] = 0.5f*s;
    }
    if (t < 2048){   // pool scale 0 (f=16): r[b][c] = mean z[b][c][:][:]
        int b = t >> 5, c = t & 31;
        const float4* p = (const float4*)(z + (b*C + c)*256);
        float s = 0.f;
        for (int k = 0; k < 64; k++){
            float4 v = p[k];
            s += v.x + v.y + v.z + v.w;
        }
        g_r[(b)*C + c] = s * (1.f/256.f);
    }
    if (t < 256){
        int s = t >> 6, rem = t & 63, Y = rem >> 2, a = rem & 3;
        int ph = 1 << s;
        float scale = (float)ph / 16.f;
        float src = ((float)Y + 0.5f)*scale - 0.5f;
        float i0 = floorf(src);
        float fr = src - i0;
        int off = a - 1;
        int idx = (int)i0 + off;
        idx = min(max(idx, 0), ph - 1);
        g_itab[s][Y][a] = idx;
        g_wtab[s][Y][a] = cubicw(fr - (float)off);
    }
}

// ---------------- area pool to [N][C] channel-last (scale 1 only) ----------------
__global__ void pool_kernel(int ph){
    int t = blockIdx.x*blockDim.x + threadIdx.x;
    int N = B*ph*ph;
    if (t >= N*C) return;
    int n = t >> 5, c = t & 31;
    int pp = ph*ph;
    int b = n / pp, rem = n % pp, y = rem / ph, x = rem % ph;
    int f = HW / ph;
    const float* base = g_zres + ((b*C + c)*HW + y*f)*HW + x*f;
    float s = 0.f;
    for (int dy = 0; dy < f; dy++)
        for (int dx = 0; dx < f; dx++)
            s += base[dy*HW + dx];
    g_r[n*C + c] = s * (1.f / (float)(f*f));
}

// ---------------- code search: score = 0.5||e||^2 - r.e, FFMA2, TROWS rows/thread ----------------
template<int TROWS>
__global__ __launch_bounds__(128) void argmin_kernel(const float* __restrict__ emb, int N, int chunk,
                                                     int base, int fmode){
    __shared__ __align__(16) float et[C*TCODES];   // transposed [dim][code]
    __shared__ __align__(16) float hs[TCODES];
    int tid = threadIdx.x;
    int row0 = blockIdx.x*(128*TROWS) + tid;
    int cbase = blockIdx.y * chunk;

    unsigned long long nrp[TROWS][C];    // packed {-r_d, -r_d}
    bool act[TROWS];
    #pragma unroll
    for (int tr = 0; tr < TROWS; tr++){
        int row = row0 + tr*128;
        act[tr] = row < N;
        if (act[tr]){
            float r[C];
            load_r(row, fmode, r);
            #pragma unroll
            for (int c = 0; c < C; c++) nrp[tr][c] = pk2(-r[c], -r[c]);
        }
    }
    float best[TROWS]; int bcode[TROWS];
    #pragma unroll
    for (int tr = 0; tr < TROWS; tr++){ best[tr] = 3.4e38f; bcode[tr] = 0; }

    for (int tb = 0; tb < chunk; tb += TCODES){
        int code = cbase + tb + tid;
        const float4* src = (const float4*)(emb + code*C);
        __syncthreads();   // prior tile fully consumed
        #pragma unroll
        for (int k = 0; k < 8; k++){
            float4 v = src[k];
            et[(4*k+0)*TCODES + tid] = v.x;
            et[(4*k+1)*TCODES + tid] = v.y;
            et[(4*k+2)*TCODES + tid] = v.z;
            et[(4*k+3)*TCODES + tid] = v.w;
        }
        hs[tid] = g_hesq[code];
        __syncthreads();

        for (int jj = 0; jj < TCODES; jj += 8){
            const ulonglong2* h2 = (const ulonglong2*)(hs + jj);
            ulonglong2 ha = h2[0], hb = h2[1];
            unsigned long long acc[TROWS][4];
            #pragma unroll
            for (int tr = 0; tr < TROWS; tr++){
                acc[tr][0] = ha.x; acc[tr][1] = ha.y; acc[tr][2] = hb.x; acc[tr][3] = hb.y;
            }
            #pragma unroll
            for (int d = 0; d < C; d++){
                const ulonglong2* e2 = (const ulonglong2*)(et + d*TCODES + jj);
                ulonglong2 ea = e2[0], eb = e2[1];
                #pragma unroll
                for (int tr = 0; tr < TROWS; tr++){
                    ffma2(acc[tr][0], nrp[tr][d], ea.x);
                    ffma2(acc[tr][1], nrp[tr][d], ea.y);
                    ffma2(acc[tr][2], nrp[tr][d], eb.x);
                    ffma2(acc[tr][3], nrp[tr][d], eb.y);
                }
            }
            #pragma unroll
            for (int tr = 0; tr < TROWS; tr++){
                float s[8] = {lo2(acc[tr][0]),hi2(acc[tr][0]),lo2(acc[tr][1]),hi2(acc[tr][1]),
                              lo2(acc[tr][2]),hi2(acc[tr][2]),lo2(acc[tr][3]),hi2(acc[tr][3])};
                #pragma unroll
                for (int k = 0; k < 8; k++){
                    int cc = cbase + tb + jj + k;
                    if (s[k] < best[tr]){ best[tr] = s[k]; bcode[tr] = cc; }
                }
            }
        }
    }
    #pragma unroll
    for (int tr = 0; tr < TROWS; tr++){
        if (act[tr]){
            unsigned long long key = ((unsigned long long)ford(best[tr]) << 32) | (unsigned)bcode[tr];
            atomicMin(&g_res64[base + row0 + tr*128], key);
        }
    }
}

// ---------------- fused gather(+bicubic) + Phi conv3x3 + residual update + loss ----------------
// R13 conv core (2oc x 4y per thread, 256 thr, grid (B,4)) with gather fused in the staging phase.
__global__ __launch_bounds__(256) void conv_update_kernel(const float* __restrict__ z,
        const float* __restrict__ emb, const float* __restrict__ w, const float* __restrict__ bias,
        int si, int ph, int base, float* __restrict__ out){
    extern __shared__ float sm[];
    float* s_in   = sm;                    // [ci][pix], stride 257
    float* s_w    = sm + 8224;             // [ci][k][oc8]
    float* red    = s_w + 2304;            // 256
    int*   s_code = (int*)(red + 256);     // 256
    float* s_q    = (float*)(s_code + 256);// [code][c+pad33]
    float* s_tmp  = s_q + 2112;            // [py*16+x][c+pad33]
    int b = blockIdx.x, og = blockIdx.y, t = threadIdx.x;
    int pp = ph*ph;

    for (int i = t; i < pp; i += 256)
        s_code[i] = (int)(g_res64[base + b*pp + i] & 0xFFFFFFFFull);
    // weights: global [oc_l][ci][k] -> smem [ci][k][oc_l]
    for (int i = t; i < 8*C*9; i += 256){
        int oc_l = i / (C*9);
        int rem  = i - oc_l*(C*9);
        s_w[rem*8 + oc_l] = w[og*8*C*9 + i];
    }
    __syncthreads();

    if (si == 4){
        // direct gather: s_in[c][pix] = emb[code[pix]*C + c]
        for (int j = t; j < IMG/4; j += 256){
            int pix = j >> 3, c0 = (j & 7)*4;
            float4 v = *(const float4*)(emb + s_code[pix]*C + c0);
            s_in[(c0+0)*257 + pix] = v.x;
            s_in[(c0+1)*257 + pix] = v.y;
            s_in[(c0+2)*257 + pix] = v.z;
            s_in[(c0+3)*257 + pix] = v.w;
        }
    } else {
        // stage q vectors: s_q[code][c] (lanes vary c -> coalesced)
        for (int i = t; i < pp*C; i += 256){
            int c = i & 31, code = i >> 5;
            s_q[code*33 + c] = emb[s_code[code]*C + c];
        }
        __syncthreads();
        // pass1: x-interp -> s_tmp[py*16+x][c]
        int n1 = ph*16*C;
        for (int i = t; i < n1; i += 256){
            int c = i & 31, x = (i >> 5) & 15, py = i >> 9;
            float acc = 0.f;
            #pragma unroll
            for (int ax = 0; ax < 4; ax++){
                int ix = g_itab[si][x][ax];
                acc += g_wtab[si][x][ax] * s_q[(py*ph + ix)*33 + c];
            }
            s_tmp[(py*16 + x)*33 + c] = acc;
        }
        __syncthreads();
        // pass2: y-interp -> s_in[c][y*16+x]
        for (int i = t; i < IMG; i += 256){
            int c = i & 31, x = (i >> 5) & 15, y = i >> 9;
            float acc = 0.f;
            #pragma unroll
            for (int ay = 0; ay < 4; ay++){
                int iy = g_itab[si][y][ay];
                acc += g_wtab[si][y][ay] * s_tmp[(iy*16 + x)*33 + c];
            }
            s_in[c*257 + y*16 + x] = acc;
        }
    }
    __syncthreads();

    int x    = t & 15;        // lane dim -> conflict-free v loads
    int yq   = (t >> 4) & 3;  // rows 4yq..4yq+3
    int ocp  = t >> 6;        // 0..3 -> oc_l = ocp*2, ocp*2+1
    int y0 = 4*yq;

    float acc[2][4];          // [oc][y]
    #pragma unroll
    for (int o = 0; o < 2; o++)
        #pragma unroll
        for (int i = 0; i < 4; i++) acc[o][i] = 0.f;

    for (int ci = 0; ci < C; ci++){
        const float* base_ci = s_in + ci*257;
        const float* wci = s_w + ci*72 + ocp*2;
        #pragma unroll
        for (int kx = 0; kx < 3; kx++){
            int xx = x + kx - 1;
            if (xx < 0 || xx >= HW) continue;   // zero pad
            float v[6];
            v[0] = (y0 >= 1)     ? base_ci[(y0-1)*16 + xx] : 0.f;
            v[1] = base_ci[(y0+0)*16 + xx];
            v[2] = base_ci[(y0+1)*16 + xx];
            v[3] = base_ci[(y0+2)*16 + xx];
            v[4] = base_ci[(y0+3)*16 + xx];
            v[5] = (y0 + 4 < HW) ? base_ci[(y0+4)*16 + xx] : 0.f;
            #pragma unroll
            for (int ky = 0; ky < 3; ky++){
                float2 w2 = *(const float2*)(wci + (ky*3 + kx)*8);   // 2 ocs, broadcast
                #pragma unroll
                for (int i = 0; i < 4; i++){
                    float vv = v[i + ky];
                    acc[0][i] += w2.x * vv;
                    acc[1][i] += w2.y * vv;
                }
            }
        }
    }

    float ls = 0.f;
    #pragma unroll
    for (int o = 0; o < 2; o++){
        int oc = og*8 + ocp*2 + o;
        float bval = bias[oc];
        int gbase = ((b*C + oc)*HW)*HW + x;
        #pragma unroll
        for (int i = 0; i < 4; i++){
            int y = y0 + i;
            float qv = 0.5f*s_in[oc*257 + y*16 + x] + 0.5f*(acc[o][i] + bval);
            int g = gbase + y*HW;
            float zr = g_zres[g] - qv;
            if (si < 4){
                g_zres[g] = zr;
            } else {
                out[g] = z[g] - zr;   // z_hat (straight-through value)
            }
            ls += zr*zr;              // (z_hat - z)^2 == zres_new^2
        }
    }
    red[t] = ls;
    __syncthreads();
    for (int s = 128; s > 0; s >>= 1){
        if (t < s) red[t] += red[t+s];
        __syncthreads();
    }
    if (t == 0) g_losspart[si*256 + b*4 + og] = red[0];
}

// ---------------- final pack: loss (parallel reduce) + idx floats ----------------
__global__ void pack_kernel(float* __restrict__ out){
    int t = blockIdx.x*blockDim.x + threadIdx.x;
    if (blockIdx.x == 0){
        __shared__ float red[256];
        float s = 0.f;
        for (int i = threadIdx.x; i < 5*256; i += 256) s += g_losspart[i];
        red[threadIdx.x] = s;
        __syncthreads();
        for (int k = 128; k > 0; k >>= 1){
            if (threadIdx.x < k) red[threadIdx.x] += red[threadIdx.x + k];
            __syncthreads();
        }
        if (threadIdx.x == 0) out[TOT] = red[0] * (1.25f / ((float)TOT * 5.f));
    }
    if (t < NIDX){
        int base, pp, ofs_row;
        if      (t <   64){ base=0;    pp=1;   ofs_row=0;  }
        else if (t <  320){ base=64;   pp=4;   ofs_row=1;  }
        else if (t < 1344){ base=320;  pp=16;  ofs_row=5;  }
        else if (t < 5440){ base=1344; pp=64;  ofs_row=21; }
        else              { base=5440; pp=256; ofs_row=85; }
        int r = t - base;
        int bb = r / pp, p = r % pp;
        int code = (int)(g_res64[t] & 0xFFFFFFFFull);
        out[TOT + 1 + bb*ROWLEN + ofs_row + p] = (float)code;
    }
}

extern "C" void kernel_launch(void* const* d_in, const int* in_sizes, int n_in,
                              void* d_out, int out_size){
    // Bind inputs by element count: z=524288, emb=131072, phi_w=36864, phi_b=128 (all distinct).
    const float* z = 0; const float* emb = 0; const float* phi_w = 0; const float* phi_b = 0;
    for (int i = 0; i < n_in; i++){
        switch (in_sizes[i]){
            case 524288: z     = (const float*)d_in[i]; break;
            case 131072: emb   = (const float*)d_in[i]; break;
            case 36864:  phi_w = (const float*)d_in[i]; break;
            case 128:    phi_b = (const float*)d_in[i]; break;
            default: break;
        }
    }
    float* out = (float*)d_out;
    (void)out_size;

    cudaFuncSetAttribute(conv_update_kernel, cudaFuncAttributeMaxDynamicSharedMemorySize, SMEM_CONV);

    setup_kernel<<<(TOT + 255)/256, 256>>>(z, emb);

    // numpy-exact Phi tick selection (float64 linspace semantics, first-wins argmin)
    double start = 1.0/12.0;
    double stop  = 1.0 - 1.0/12.0;
    double step  = (stop - start) / 3.0;
    double ticks[4];
    for (int i = 0; i < 4; i++) ticks[i] = (double)i * step + start;
    ticks[3] = stop;
    int pis[5];
    for (int si = 0; si < 5; si++){
        double target = (double)si / 4.0;
        int bestp = 0; double bestd = fabs(ticks[0] - target);
        for (int p = 1; p < 4; p++){
            double d = fabs(ticks[p] - target);
            if (d < bestd){ bestd = d; bestp = p; }
        }
        pis[si] = bestp;
    }

    const int scales[5] = {1, 2, 4, 8, 16};
    const int iofs[5]   = {0, 64, 320, 1344, 5440};
    const int splits[5] = {32, 32, 16, 16, 8};
    const int fmodes[5] = {0, 0, 3, 2, 1};

    for (int si = 0; si < 5; si++){
        int ph = scales[si];
        int N  = B*ph*ph;
        if (si == 1) pool_kernel<<<(N*C + 255)/256, 256>>>(ph);
        int chunk = NE/splits[si];
        if (si >= 3){
            dim3 g((N + 255)/256, splits[si]);
            argmin_kernel<2><<<g, 128>>>(emb, N, chunk, iofs[si], fmodes[si]);
        } else {
            dim3 g((N + 127)/128, splits[si]);
            argmin_kernel<1><<<g, 128>>>(emb, N, chunk, iofs[si], fmodes[si]);
        }
        conv_update_kernel<<<dim3(B, 4), 256, SMEM_CONV>>>(
            z, emb, phi_w + pis[si]*C*C*9, phi_b + pis[si]*C,
            si, ph, iofs[si], (si == 4) ? out : (float*)0);
    }
    pack_kernel<<<(NIDX + 255)/256, 256>>>(out);
}

// round 16
// speedup vs baseline: 1.2023x; 1.0613x over previous
#include <cuda_runtime.h>
#include <cmath>

#define B 64
#define C 32
#define HW 16
#define IMG (C*HW*HW)        // 8192
#define TOT (B*IMG)          // 524288
#define NE 4096
#define NIDX 21824
#define ROWLEN 341
#define TCODES 128

// dynamic smem floats: s_in 8224 | s_w 2304 | red 256 | s_code 256(int) | s_q 2112 | s_tmp 4224
#define SMEM_CONV ((8224 + 2304 + 256 + 256 + 2112 + 4224) * 4)

// ---------------- scratch (no allocations allowed) ----------------
__device__ float g_zres[TOT];
__device__ float g_r[TOT];            // only scales 0..1 use this
__device__ float g_hesq[NE];          // 0.5*||e||^2
__device__ unsigned long long g_res64[NIDX];
__device__ float g_losspart[5*256];
__device__ int   g_itab[4][16][4];
__device__ float g_wtab[4][16][4];

// ---------------- helpers ----------------
__device__ __forceinline__ float cubicw(float x){
    const float A = -0.75f;
    x = fabsf(x);
    if (x <= 1.f) return ((A + 2.f)*x - (A + 3.f))*x*x + 1.f;
    if (x < 2.f)  return A*(((x - 5.f)*x + 8.f)*x - 4.f);
    return 0.f;
}
__device__ __forceinline__ void ffma2(unsigned long long &d, unsigned long long a, unsigned long long b){
    asm("fma.rn.f32x2 %0, %1, %2, %0;" : "+l"(d) : "l"(a), "l"(b));
}
__device__ __forceinline__ unsigned long long pk2(float a, float b){
    return ((unsigned long long)__float_as_uint(b) << 32) | (unsigned long long)__float_as_uint(a);
}
__device__ __forceinline__ float lo2(unsigned long long v){ return __uint_as_float((unsigned)v); }
__device__ __forceinline__ float hi2(unsigned long long v){ return __uint_as_float((unsigned)(v >> 32)); }
__device__ __forceinline__ unsigned ford(float f){
    unsigned u = __float_as_uint(f);
    return (u & 0x80000000u) ? ~u : (u | 0x80000000u);
}

// pooled residual row loader. fmode: 0 = g_r, 1 = f=1, 2 = f=2, 3 = f=4
__device__ __forceinline__ void load_r(int row, int fmode, float* r){
    if (fmode == 1){
        int bb = row >> 8, rem = row & 255;
        const float* p = g_zres + bb*IMG + rem;
        #pragma unroll
        for (int c = 0; c < C; c++) r[c] = p[c*256];
    } else if (fmode == 2){
        int bb = row >> 6, rem = row & 63;
        int y = rem >> 3, x = rem & 7;
        const float* p = g_zres + bb*IMG + (2*y)*16 + 2*x;
        #pragma unroll
        for (int c = 0; c < C; c++){
            const float* q = p + c*256;
            r[c] = (q[0] + q[1] + q[16] + q[17]) * 0.25f;
        }
    } else if (fmode == 3){
        int bb = row >> 4, rem = row & 15;
        int y = rem >> 2, x = rem & 3;
        const float* p = g_zres + bb*IMG + (4*y)*16 + 4*x;
        #pragma unroll
        for (int c = 0; c < C; c++){
            const float* q = p + c*256;
            float s = 0.f;
            #pragma unroll
            for (int dy = 0; dy < 4; dy++){
                s += q[dy*16 + 0]; s += q[dy*16 + 1]; s += q[dy*16 + 2]; s += q[dy*16 + 3];
            }
            r[c] = s * 0.0625f;
        }
    } else {
        const float4* rp = (const float4*)(g_r + row*C);
        #pragma unroll
        for (int k = 0; k < 8; k++){
            float4 v = rp[k];
            r[4*k+0] = v.x; r[4*k+1] = v.y; r[4*k+2] = v.z; r[4*k+3] = v.w;
        }
    }
}

// ---------------- setup (also pools scale 0, whose input is raw z) ----------------
__global__ void setup_kernel(const float* __restrict__ z, const float* __restrict__ emb){
    int t = blockIdx.x*blockDim.x + threadIdx.x;
    if (t < TOT) g_zres[t] = z[t];
    if (t < NIDX) g_res64[t] = 0xFFFFFFFFFFFFFFFFull;
    if (t < NE){
        float s = 0.f;
        #pragma unroll
        for (int k = 0; k < C; k++){ float e = emb[t*C + k]; s += e*e; }
        g_hesq[t] = 0.5f*s;
    }
    if (t < 2048){   // pool scale 0 (f=16): r[b][c] = mean z[b][c][:][:]
        int b = t >> 5, c = t & 31;
        const float4* p = (const float4*)(z + (b*C + c)*256);
        float s = 0.f;
        for (int k = 0; k < 64; k++){
            float4 v = p[k];
            s += v.x + v.y + v.z + v.w;
        }
        g_r[(b)*C + c] = s * (1.f/256.f);
    }
    if (t < 256){
        int s = t >> 6, rem = t & 63, Y = rem >> 2, a = rem & 3;
        int ph = 1 << s;
        float scale = (float)ph / 16.f;
        float src = ((float)Y + 0.5f)*scale - 0.5f;
        float i0 = floorf(src);
        float fr = src - i0;
        int off = a - 1;
        int idx = (int)i0 + off;
        idx = min(max(idx, 0), ph - 1);
        g_itab[s][Y][a] = idx;
        g_wtab[s][Y][a] = cubicw(fr - (float)off);
    }
}

// ---------------- pool for scale 1 (f=8): 4 threads/output, float4 + shfl ----------------
__global__ void pool_kernel(){
    int tg = blockIdx.x*blockDim.x + threadIdx.x;   // 32768 threads
    int out_idx = tg >> 2, sub = tg & 3;
    int n = out_idx >> 5, c = out_idx & 31;
    int b = n >> 2, rem = n & 3, y = rem >> 1, x = rem & 1;
    // rows sub*2, sub*2+1 of the 8x8 region; 2 float4 per row
    const float4* p = (const float4*)(g_zres + ((b*C + c)*HW + y*8 + sub*2)*HW + x*8);
    float4 a = p[0], bq = p[1], cq = p[4], dq = p[5];
    float s = a.x+a.y+a.z+a.w + bq.x+bq.y+bq.z+bq.w
            + cq.x+cq.y+cq.z+cq.w + dq.x+dq.y+dq.z+dq.w;
    s += __shfl_xor_sync(0xFFFFFFFFu, s, 1);
    s += __shfl_xor_sync(0xFFFFFFFFu, s, 2);
    if (sub == 0) g_r[out_idx] = s * (1.f/64.f);
}

// ---------------- code search: score = 0.5||e||^2 - r.e, FFMA2, TROWS rows/thread ----------------
template<int TROWS>
__global__ __launch_bounds__(128) void argmin_kernel(const float* __restrict__ emb, int N, int chunk,
                                                     int base, int fmode){
    __shared__ __align__(16) float et[C*TCODES];   // transposed [dim][code]
    __shared__ __align__(16) float hs[TCODES];
    int tid = threadIdx.x;
    int row0 = blockIdx.x*(128*TROWS) + tid;
    int cbase = blockIdx.y * chunk;

    unsigned long long nrp[TROWS][C];    // packed {-r_d, -r_d}
    bool act[TROWS];
    #pragma unroll
    for (int tr = 0; tr < TROWS; tr++){
        int row = row0 + tr*128;
        act[tr] = row < N;
        if (act[tr]){
            float r[C];
            load_r(row, fmode, r);
            #pragma unroll
            for (int c = 0; c < C; c++) nrp[tr][c] = pk2(-r[c], -r[c]);
        }
    }
    float best[TROWS]; int bcode[TROWS];
    #pragma unroll
    for (int tr = 0; tr < TROWS; tr++){ best[tr] = 3.4e38f; bcode[tr] = 0; }

    for (int tb = 0; tb < chunk; tb += TCODES){
        int code = cbase + tb + tid;
        const float4* src = (const float4*)(emb + code*C);
        __syncthreads();   // prior tile fully consumed
        #pragma unroll
        for (int k = 0; k < 8; k++){
            float4 v = src[k];
            et[(4*k+0)*TCODES + tid] = v.x;
            et[(4*k+1)*TCODES + tid] = v.y;
            et[(4*k+2)*TCODES + tid] = v.z;
            et[(4*k+3)*TCODES + tid] = v.w;
        }
        hs[tid] = g_hesq[code];
        __syncthreads();

        for (int jj = 0; jj < TCODES; jj += 8){
            const ulonglong2* h2 = (const ulonglong2*)(hs + jj);
            ulonglong2 ha = h2[0], hb = h2[1];
            unsigned long long acc[TROWS][4];
            #pragma unroll
            for (int tr = 0; tr < TROWS; tr++){
                acc[tr][0] = ha.x; acc[tr][1] = ha.y; acc[tr][2] = hb.x; acc[tr][3] = hb.y;
            }
            #pragma unroll
            for (int d = 0; d < C; d++){
                const ulonglong2* e2 = (const ulonglong2*)(et + d*TCODES + jj);
                ulonglong2 ea = e2[0], eb = e2[1];
                #pragma unroll
                for (int tr = 0; tr < TROWS; tr++){
                    ffma2(acc[tr][0], nrp[tr][d], ea.x);
                    ffma2(acc[tr][1], nrp[tr][d], ea.y);
                    ffma2(acc[tr][2], nrp[tr][d], eb.x);
                    ffma2(acc[tr][3], nrp[tr][d], eb.y);
                }
            }
            #pragma unroll
            for (int tr = 0; tr < TROWS; tr++){
                float s[8] = {lo2(acc[tr][0]),hi2(acc[tr][0]),lo2(acc[tr][1]),hi2(acc[tr][1]),
                              lo2(acc[tr][2]),hi2(acc[tr][2]),lo2(acc[tr][3]),hi2(acc[tr][3])};
                #pragma unroll
                for (int k = 0; k < 8; k++){
                    int cc = cbase + tb + jj + k;
                    if (s[k] < best[tr]){ best[tr] = s[k]; bcode[tr] = cc; }
                }
            }
        }
    }
    #pragma unroll
    for (int tr = 0; tr < TROWS; tr++){
        if (act[tr]){
            unsigned long long key = ((unsigned long long)ford(best[tr]) << 32) | (unsigned)bcode[tr];
            atomicMin(&g_res64[base + row0 + tr*128], key);
        }
    }
}

// ---------------- fused gather(+bicubic) + Phi conv3x3 + residual update + loss + idx ----------------
__global__ __launch_bounds__(256) void conv_update_kernel(const float* __restrict__ z,
        const float* __restrict__ emb, const float* __restrict__ w, const float* __restrict__ bias,
        int si, int ph, int base, int idx_row_ofs, float* __restrict__ out){
    extern __shared__ float sm[];
    float* s_in   = sm;                    // [ci][pix], stride 257
    float* s_w    = sm + 8224;             // [ci][k][oc8]
    float* red    = s_w + 2304;            // 256
    int*   s_code = (int*)(red + 256);     // 256
    float* s_q    = (float*)(s_code + 256);// [code][c+pad33]; si=0: s_q[c]
    float* s_tmp  = s_q + 2112;            // [py*16+x][c+pad33]; si=0: A[k*8+oc]
    int b = blockIdx.x, og = blockIdx.y, t = threadIdx.x;
    int pp = ph*ph;

    for (int i = t; i < pp; i += 256)
        s_code[i] = (int)(g_res64[base + b*pp + i] & 0xFFFFFFFFull);
    // weights: global [oc_l][ci][k] -> smem [ci][k][oc_l]
    for (int i = t; i < 8*C*9; i += 256){
        int oc_l = i / (C*9);
        int rem  = i - oc_l*(C*9);
        s_w[rem*8 + oc_l] = w[og*8*C*9 + i];
    }
    __syncthreads();

    // fused idx output (codes are final here); og==0 block writes this batch/scale
    if (og == 0){
        for (int i = t; i < pp; i += 256)
            out[TOT + 1 + b*ROWLEN + idx_row_ofs + i] = (float)s_code[i];
    }

    if (si == 0){
        // constant image: q_up[c][*] == q[c]; conv = border-masked tap sums
        if (t < C) s_q[t] = emb[s_code[0]*C + t];
        __syncthreads();
        if (t < 72){            // A[k*8 + oc_l] = sum_ci q[ci] * w[oc][ci][k]
            int k = t >> 3, oc_l = t & 7;
            float a = 0.f;
            #pragma unroll
            for (int ci = 0; ci < C; ci++) a += s_q[ci] * s_w[ci*72 + k*8 + oc_l];
            s_tmp[t] = a;
        }
    } else if (si == 4){
        // direct gather: s_in[c][pix] = emb[code[pix]*C + c]
        for (int j = t; j < IMG/4; j += 256){
            int pix = j >> 3, c0 = (j & 7)*4;
            float4 v = *(const float4*)(emb + s_code[pix]*C + c0);
            s_in[(c0+0)*257 + pix] = v.x;
            s_in[(c0+1)*257 + pix] = v.y;
            s_in[(c0+2)*257 + pix] = v.z;
            s_in[(c0+3)*257 + pix] = v.w;
        }
    } else {
        // stage q vectors: s_q[code][c] (lanes vary c -> coalesced)
        for (int i = t; i < pp*C; i += 256){
            int c = i & 31, code = i >> 5;
            s_q[code*33 + c] = emb[s_code[code]*C + c];
        }
        __syncthreads();
        // pass1: x-interp -> s_tmp[py*16+x][c]
        int n1 = ph*16*C;
        for (int i = t; i < n1; i += 256){
            int c = i & 31, x = (i >> 5) & 15, py = i >> 9;
            float acc = 0.f;
            #pragma unroll
            for (int ax = 0; ax < 4; ax++){
                int ix = g_itab[si][x][ax];
                acc += g_wtab[si][x][ax] * s_q[(py*ph + ix)*33 + c];
            }
            s_tmp[(py*16 + x)*33 + c] = acc;
        }
        __syncthreads();
        // pass2: y-interp -> s_in[c][y*16+x]
        for (int i = t; i < IMG; i += 256){
            int c = i & 31, x = (i >> 5) & 15, y = i >> 9;
            float acc = 0.f;
            #pragma unroll
            for (int ay = 0; ay < 4; ay++){
                int iy = g_itab[si][y][ay];
                acc += g_wtab[si][y][ay] * s_tmp[(iy*16 + x)*33 + c];
            }
            s_in[c*257 + y*16 + x] = acc;
        }
    }
    __syncthreads();

    int x    = t & 15;        // lane dim -> conflict-free v loads
    int yq   = (t >> 4) & 3;  // rows 4yq..4yq+3
    int ocp  = t >> 6;        // 0..3 -> oc_l = ocp*2, ocp*2+1
    int y0 = 4*yq;

    float acc[2][4];          // [oc][y]
    #pragma unroll
    for (int o = 0; o < 2; o++)
        #pragma unroll
        for (int i = 0; i < 4; i++) acc[o][i] = 0.f;

    if (si == 0){
        #pragma unroll
        for (int o = 0; o < 2; o++){
            int ocl = ocp*2 + o;
            #pragma unroll
            for (int i = 0; i < 4; i++){
                int y = y0 + i;
                float a = 0.f;
                #pragma unroll
                for (int ky = 0; ky < 3; ky++){
                    int yy = y + ky - 1;
                    if (yy < 0 || yy >= HW) continue;
                    #pragma unroll
                    for (int kx = 0; kx < 3; kx++){
                        int xx = x + kx - 1;
                        if (xx < 0 || xx >= HW) continue;
                        a += s_tmp[(ky*3 + kx)*8 + ocl];
                    }
                }
                acc[o][i] = a;
            }
        }
    } else {
        for (int ci = 0; ci < C; ci++){
            const float* base_ci = s_in + ci*257;
            const float* wci = s_w + ci*72 + ocp*2;
            #pragma unroll
            for (int kx = 0; kx < 3; kx++){
                int xx = x + kx - 1;
                if (xx < 0 || xx >= HW) continue;   // zero pad
                float v[6];
                v[0] = (y0 >= 1)     ? base_ci[(y0-1)*16 + xx] : 0.f;
                v[1] = base_ci[(y0+0)*16 + xx];
                v[2] = base_ci[(y0+1)*16 + xx];
                v[3] = base_ci[(y0+2)*16 + xx];
                v[4] = base_ci[(y0+3)*16 + xx];
                v[5] = (y0 + 4 < HW) ? base_ci[(y0+4)*16 + xx] : 0.f;
                #pragma unroll
                for (int ky = 0; ky < 3; ky++){
                    float2 w2 = *(const float2*)(wci + (ky*3 + kx)*8);   // 2 ocs, broadcast
                    #pragma unroll
                    for (int i = 0; i < 4; i++){
                        float vv = v[i + ky];
                        acc[0][i] += w2.x * vv;
                        acc[1][i] += w2.y * vv;
                    }
                }
            }
        }
    }

    float ls = 0.f;
    #pragma unroll
    for (int o = 0; o < 2; o++){
        int oc = og*8 + ocp*2 + o;
        float bval = bias[oc];
        int gbase = ((b*C + oc)*HW)*HW + x;
        #pragma unroll
        for (int i = 0; i < 4; i++){
            int y = y0 + i;
            float qin = (si == 0) ? s_q[oc] : s_in[oc*257 + y*16 + x];
            float qv = 0.5f*qin + 0.5f*(acc[o][i] + bval);
            int g = gbase + y*HW;
            float zr = g_zres[g] - qv;
            if (si < 4){
                g_zres[g] = zr;
            } else {
                out[g] = z[g] - zr;   // z_hat (straight-through value)
            }
            ls += zr*zr;              // (z_hat - z)^2 == zres_new^2
        }
    }
    red[t] = ls;
    __syncthreads();
    for (int s = 128; s > 0; s >>= 1){
        if (t < s) red[t] += red[t+s];
        __syncthreads();
    }
    if (t == 0) g_losspart[si*256 + b*4 + og] = red[0];
}

// ---------------- final pack: loss only (single block) ----------------
__global__ void pack_kernel(float* __restrict__ out){
    __shared__ float red[256];
    float s = 0.f;
    for (int i = threadIdx.x; i < 5*256; i += 256) s += g_losspart[i];
    red[threadIdx.x] = s;
    __syncthreads();
    for (int k = 128; k > 0; k >>= 1){
        if (threadIdx.x < k) red[threadIdx.x] += red[threadIdx.x + k];
        __syncthreads();
    }
    if (threadIdx.x == 0) out[TOT] = red[0] * (1.25f / ((float)TOT * 5.f));
}

extern "C" void kernel_launch(void* const* d_in, const int* in_sizes, int n_in,
                              void* d_out, int out_size){
    // Bind inputs by element count: z=524288, emb=131072, phi_w=36864, phi_b=128 (all distinct).
    const float* z = 0; const float* emb = 0; const float* phi_w = 0; const float* phi_b = 0;
    for (int i = 0; i < n_in; i++){
        switch (in_sizes[i]){
            case 524288: z     = (const float*)d_in[i]; break;
            case 131072: emb   = (const float*)d_in[i]; break;
            case 36864:  phi_w = (const float*)d_in[i]; break;
            case 128:    phi_b = (const float*)d_in[i]; break;
            default: break;
        }
    }
    float* out = (float*)d_out;
    (void)out_size;

    cudaFuncSetAttribute(conv_update_kernel, cudaFuncAttributeMaxDynamicSharedMemorySize, SMEM_CONV);

    setup_kernel<<<(TOT + 255)/256, 256>>>(z, emb);

    // numpy-exact Phi tick selection (float64 linspace semantics, first-wins argmin)
    double start = 1.0/12.0;
    double stop  = 1.0 - 1.0/12.0;
    double step  = (stop - start) / 3.0;
    double ticks[4];
    for (int i = 0; i < 4; i++) ticks[i] = (double)i * step + start;
    ticks[3] = stop;
    int pis[5];
    for (int si = 0; si < 5; si++){
        double target = (double)si / 4.0;
        int bestp = 0; double bestd = fabs(ticks[0] - target);
        for (int p = 1; p < 4; p++){
            double d = fabs(ticks[p] - target);
            if (d < bestd){ bestd = d; bestp = p; }
        }
        pis[si] = bestp;
    }

    const int scales[5] = {1, 2, 4, 8, 16};
    const int iofs[5]   = {0, 64, 320, 1344, 5440};
    const int rofs[5]   = {0, 1, 5, 21, 85};
    const int splits[5] = {32, 32, 16, 16, 8};
    const int fmodes[5] = {0, 0, 3, 2, 1};

    for (int si = 0; si < 5; si++){
        int ph = scales[si];
        int N  = B*ph*ph;
        if (si == 1) pool_kernel<<<128, 256>>>();
        int chunk = NE/splits[si];
        if (si >= 3){
            dim3 g((N + 255)/256, splits[si]);
            argmin_kernel<2><<<g, 128>>>(emb, N, chunk, iofs[si], fmodes[si]);
        } else {
            dim3 g((N + 127)/128, splits[si]);
            argmin_kernel<1><<<g, 128>>>(emb, N, chunk, iofs[si], fmodes[si]);
        }
        conv_update_kernel<<<dim3(B, 4), 256, SMEM_CONV>>>(
            z, emb, phi_w + pis[si]*C*C*9, phi_b + pis[si]*C,
            si, ph, iofs[si], rofs[si], out);
    }
    pack_kernel<<<1, 256>>>(out);
}